// round 3
// baseline (speedup 1.0000x reference)
#include <cuda_runtime.h>
#include <cstdint>

#define N_NODES 50000
#define N_EDGES 500000
#define D_NODE  128
#define D_EDGE  64
#define D_HID   256
#define D_OUT   64

// Precomputed node-term table: P[node][0:256] = nf@W1a + b1, P[node][256:512] = nf@W1b
__device__ float g_P[(size_t)N_NODES * 512];

// edge_index dtype mode: 1 = int64 (8-byte stride), 0 = int32 (4-byte stride)
__device__ int g_idx64;

// ---------------------------------------------------------------------------
// Detect whether edge_index is int64 or int32 by inspecting raw 32-bit words.
// int64 layout: every odd word is the (zero) high half of a small nonnegative
// value. int32 layout: odd words are random node ids, overwhelmingly nonzero.
// ---------------------------------------------------------------------------
__global__ void k_detect(const int* __restrict__ EIw) {
    if (threadIdx.x == 0 && blockIdx.x == 0) {
        int allzero = 1;
        #pragma unroll 1
        for (int i = 0; i < 64; i++)
            if (EIw[2 * i + 1] != 0) { allzero = 0; break; }
        g_idx64 = allzero;
    }
}

// ---------------------------------------------------------------------------
// Kernel 1: P = node_feats @ [W1_a | W1_b]   (M=50000, N=512, K=128)
// 128x128 tile, 256 threads, 8x8 micro-tile with strided-n mapping.
// b1 folded into the Pa half so the edge kernel adds it exactly once.
// ---------------------------------------------------------------------------
__global__ __launch_bounds__(256) void k_precompute(
    const float* __restrict__ NF, const float* __restrict__ W1,
    const float* __restrict__ b1)
{
    const int bm = blockIdx.x;   // node tile (128 rows)
    const int bn = blockIdx.y;   // P-column tile (128 of 512)
    const int tid = threadIdx.x;
    const int tx = tid & 15, ty = tid >> 4;

    __shared__ float sA[16][130];   // [k][m], padded: conflict-free transpose store
    __shared__ float sB[16][128];   // [k][n]

    const int m0 = bm * 128;
    const int rowoff = (bn < 2) ? 0 : 128;   // W1 row block (a vs b)
    const int wc0 = (bn & 1) * 128;          // W1 col base within 256

    float c[8][8];
    #pragma unroll
    for (int i = 0; i < 8; i++)
        #pragma unroll
        for (int j = 0; j < 8; j++) c[i][j] = 0.f;

    for (int k0 = 0; k0 < D_NODE; k0 += 16) {
        #pragma unroll
        for (int t = 0; t < 8; t++) {          // A tile: 128x16
            int idx = tid + t * 256;
            int m = idx >> 4, k = idx & 15;
            int gm = m0 + m;
            sA[k][m] = (gm < N_NODES) ? NF[(size_t)gm * D_NODE + k0 + k] : 0.f;
        }
        #pragma unroll
        for (int t = 0; t < 8; t++) {          // B tile: 16x128
            int idx = tid + t * 256;
            int kk = idx >> 7, n = idx & 127;
            sB[kk][n] = W1[(size_t)(rowoff + k0 + kk) * D_HID + wc0 + n];
        }
        __syncthreads();
        #pragma unroll
        for (int kk = 0; kk < 16; kk++) {
            float a[8], b[8];
            #pragma unroll
            for (int i = 0; i < 8; i++) a[i] = sA[kk][ty * 8 + i];
            #pragma unroll
            for (int j = 0; j < 8; j++) b[j] = sB[kk][tx + 16 * j];
            #pragma unroll
            for (int i = 0; i < 8; i++)
                #pragma unroll
                for (int j = 0; j < 8; j++) c[i][j] = fmaf(a[i], b[j], c[i][j]);
        }
        __syncthreads();
    }

    #pragma unroll
    for (int i = 0; i < 8; i++) {
        int gm = m0 + ty * 8 + i;
        if (gm < N_NODES) {
            #pragma unroll
            for (int j = 0; j < 8; j++) {
                int pcol = bn * 128 + tx + 16 * j;
                float v = c[i][j];
                if (pcol < 256) v += b1[pcol];   // fold b1 into Pa
                g_P[(size_t)gm * 512 + pcol] = v;
            }
        }
    }
}

// ---------------------------------------------------------------------------
// Kernel 2: fused per-edge-tile (128 edges / CTA):
//   G = ea @ W1_c                       (128x256, K=64)
//   h = relu(G + P_a[row] + P_b[col])   (gather-add from L2-resident table)
//   out = h @ W2 + b2                   (128x64,  K=256)
// 256 threads; dynamic smem ~193 KB -> 1 CTA/SM.
// ---------------------------------------------------------------------------
__global__ __launch_bounds__(256) void k_edge(
    const int* __restrict__ EIw, const float* __restrict__ EA,
    const float* __restrict__ W1, const float* __restrict__ W2,
    const float* __restrict__ b2, float* __restrict__ out)
{
    extern __shared__ float smem[];
    float* sH  = smem;                  // [256][129] h transposed: [hid][edge]
    float* sEA = sH + 256 * 129;        // [64][129]  ea transposed: [k][edge]
    float* sB  = sEA + 64 * 129;        // [64][128]  W1c half tile
    float* sW2 = sEA;                   // reused in GEMM2: [64][64] chunks

    __shared__ int sRow[128], sCol[128];

    const int tid = threadIdx.x;
    const int tx = tid & 15, ty = tid >> 4;
    const int e0 = blockIdx.x * 128;

    if (tid < 128) {
        int e = e0 + tid;
        int r = 0, c = 0;
        if (e < N_EDGES) {
            if (g_idx64) {               // int64: value is the low 32-bit word
                r = EIw[(size_t)2 * e];
                c = EIw[(size_t)2 * (N_EDGES + e)];
            } else {                     // int32
                r = EIw[e];
                c = EIw[(size_t)N_EDGES + e];
            }
        }
        // clamp: any residual dtype surprise becomes a rel_err, not an IMA
        sRow[tid] = min(max(r, 0), N_NODES - 1);
        sCol[tid] = min(max(c, 0), N_NODES - 1);
    }
    #pragma unroll
    for (int t = 0; t < 32; t++) {       // edge_attr tile 128x64, transposed
        int idx = tid + t * 256;
        int e = idx >> 6, k = idx & 63;
        int ge = e0 + e;
        float v = (ge < N_EDGES) ? EA[(size_t)ge * D_EDGE + k] : 0.f;
        sEA[k * 129 + e] = v;
    }
    __syncthreads();

    // ---- GEMM1 + gather-add epilogue, two 128-wide hidden halves ----
    for (int half = 0; half < 2; half++) {
        const int n0 = half * 128;
        #pragma unroll
        for (int t = 0; t < 32; t++) {   // W1_c half tile: [64][128]
            int idx = tid + t * 256;
            int kk = idx >> 7, n = idx & 127;
            sB[kk * 128 + n] = W1[(size_t)(256 + kk) * D_HID + n0 + n];
        }
        __syncthreads();

        float c[8][8];
        #pragma unroll
        for (int i = 0; i < 8; i++)
            #pragma unroll
            for (int j = 0; j < 8; j++) c[i][j] = 0.f;

        #pragma unroll 16
        for (int kk = 0; kk < 64; kk++) {
            float a[8], b[8];
            #pragma unroll
            for (int i = 0; i < 8; i++) a[i] = sEA[kk * 129 + ty * 8 + i];
            #pragma unroll
            for (int j = 0; j < 8; j++) b[j] = sB[kk * 128 + tx + 16 * j];
            #pragma unroll
            for (int i = 0; i < 8; i++)
                #pragma unroll
                for (int j = 0; j < 8; j++) c[i][j] = fmaf(a[i], b[j], c[i][j]);
        }

        // epilogue: add precomputed node terms (L2 gather), relu, store to sH
        #pragma unroll
        for (int i = 0; i < 8; i++) {
            int e = ty * 8 + i;
            const float* pa = g_P + (size_t)sRow[e] * 512 + n0;         // Pa(+b1)
            const float* pb = g_P + (size_t)sCol[e] * 512 + 256 + n0;   // Pb
            #pragma unroll
            for (int j = 0; j < 8; j++) {
                int n = tx + 16 * j;
                float v = c[i][j] + __ldg(pa + n) + __ldg(pb + n);
                sH[(n0 + n) * 129 + e] = fmaxf(v, 0.f);
            }
        }
        __syncthreads();
    }

    // ---- GEMM2: out = h @ W2, K=256 in 4 chunks of 64 ----
    float d[8][4];
    #pragma unroll
    for (int i = 0; i < 8; i++)
        #pragma unroll
        for (int j = 0; j < 4; j++) d[i][j] = 0.f;

    for (int kc = 0; kc < 4; kc++) {
        const int kbase = kc * 64;
        #pragma unroll
        for (int t = 0; t < 16; t++) {   // W2 chunk [64][64]
            int idx = tid + t * 256;
            int kk = idx >> 6, n = idx & 63;
            sW2[kk * 64 + n] = W2[(size_t)(kbase + kk) * D_OUT + n];
        }
        __syncthreads();
        #pragma unroll 16
        for (int kk = 0; kk < 64; kk++) {
            float a[8], b[4];
            #pragma unroll
            for (int i = 0; i < 8; i++) a[i] = sH[(kbase + kk) * 129 + ty * 8 + i];
            #pragma unroll
            for (int j = 0; j < 4; j++) b[j] = sW2[kk * 64 + tx + 16 * j];
            #pragma unroll
            for (int i = 0; i < 8; i++)
                #pragma unroll
                for (int j = 0; j < 4; j++) d[i][j] = fmaf(a[i], b[j], d[i][j]);
        }
        __syncthreads();
    }

    #pragma unroll
    for (int i = 0; i < 8; i++) {
        int ge = e0 + ty * 8 + i;
        if (ge < N_EDGES) {
            #pragma unroll
            for (int j = 0; j < 4; j++) {
                int n = tx + 16 * j;
                out[(size_t)ge * D_OUT + n] = d[i][j] + b2[n];
            }
        }
    }
}

// ---------------------------------------------------------------------------
extern "C" void kernel_launch(void* const* d_in, const int* in_sizes, int n_in,
                              void* d_out, int out_size) {
    const float* NF  = (const float*)d_in[0];
    const int*   EIw = (const int*)d_in[1];     // raw words; dtype detected on-device
    const float* EA  = (const float*)d_in[2];
    const float* W1  = (const float*)d_in[3];
    const float* b1  = (const float*)d_in[4];
    const float* W2  = (const float*)d_in[5];
    const float* b2  = (const float*)d_in[6];
    float* out = (float*)d_out;

    const size_t smem2 = (size_t)(256 * 129 + 64 * 129 + 64 * 128) * sizeof(float); // 197,888 B
    cudaFuncSetAttribute(k_edge, cudaFuncAttributeMaxDynamicSharedMemorySize, (int)smem2);

    k_detect<<<1, 32>>>(EIw);
    dim3 g1((N_NODES + 127) / 128, 4);
    k_precompute<<<g1, 256>>>(NF, W1, b1);
    k_edge<<<(N_EDGES + 127) / 128, 256, smem2>>>(EIw, EA, W1, W2, b2, out);
}

// round 4
// speedup vs baseline: 1.9219x; 1.9219x over previous
#include <cuda_runtime.h>
#include <cuda_bf16.h>
#include <cstdint>

#define N_NODES 50000
#define N_EDGES 500000
#define D_NODE  128
#define D_EDGE  64
#define D_HID   256
#define D_OUT   64

// P[node][0:256] = nf@W1a + b1 ; P[node][256:512] = nf@W1b
__device__ float g_P[(size_t)N_NODES * 512];
// W1^T bf16 split, 5 k-panels of [256 n][64 k], SW128-swizzled 128B rows
__device__ __nv_bfloat16 gW1T_h[5 * 256 * 64];
__device__ __nv_bfloat16 gW1T_l[5 * 256 * 64];
// W2^T bf16 split, 4 k-panels of [64 n][64 k]
__device__ __nv_bfloat16 gW2T_h[4 * 64 * 64];
__device__ __nv_bfloat16 gW2T_l[4 * 64 * 64];
__device__ int g_idx64;

// ---------------- helpers ----------------
__device__ __forceinline__ uint32_t s2u(const void* p) {
    return (uint32_t)__cvta_generic_to_shared(p);
}
// swizzled byte offset inside a panel: 128B rows, XOR key (row&7)<<4
__device__ __forceinline__ uint32_t pswz(uint32_t row, uint32_t kbyte) {
    return row * 128u + (kbyte ^ ((row & 7u) << 4));
}
__device__ __forceinline__ void ldm_x4(uint32_t* r, uint32_t addr) {
    asm volatile("ldmatrix.sync.aligned.m8n8.x4.shared.b16 {%0,%1,%2,%3}, [%4];"
        : "=r"(r[0]), "=r"(r[1]), "=r"(r[2]), "=r"(r[3]) : "r"(addr));
}
__device__ __forceinline__ void mma16816(float* c, const uint32_t* a, const uint32_t* b) {
    asm volatile("mma.sync.aligned.m16n8k16.row.col.f32.bf16.bf16.f32 "
        "{%0,%1,%2,%3}, {%4,%5,%6,%7}, {%8,%9}, {%0,%1,%2,%3};"
        : "+f"(c[0]), "+f"(c[1]), "+f"(c[2]), "+f"(c[3])
        : "r"(a[0]), "r"(a[1]), "r"(a[2]), "r"(a[3]), "r"(b[0]), "r"(b[1]));
}
__device__ __forceinline__ uint32_t packbf(float a, float b) {
    __nv_bfloat162 t;
    t.x = __float2bfloat16_rn(a); t.y = __float2bfloat16_rn(b);
    return *reinterpret_cast<uint32_t*>(&t);
}
__device__ __forceinline__ void split2(float a, float b, uint32_t& hi, uint32_t& lo) {
    __nv_bfloat16 ha = __float2bfloat16_rn(a), hb = __float2bfloat16_rn(b);
    float la = a - __bfloat162float(ha), lb = b - __bfloat162float(hb);
    __nv_bfloat162 th; th.x = ha; th.y = hb;
    hi = *reinterpret_cast<uint32_t*>(&th);
    lo = packbf(la, lb);
}

// ---------------- dtype detect ----------------
__global__ void k_detect(const int* __restrict__ EIw) {
    if (threadIdx.x == 0 && blockIdx.x == 0) {
        int allzero = 1;
        #pragma unroll 1
        for (int i = 0; i < 64; i++)
            if (EIw[2 * i + 1] != 0) { allzero = 0; break; }
        g_idx64 = allzero;
    }
}

// ---------------- weight conversion: transposed + swizzled bf16 panels ----
__global__ __launch_bounds__(256) void k_convw(
    const float* __restrict__ W1, const float* __restrict__ W2)
{
    int idx = blockIdx.x * 256 + threadIdx.x;
    if (idx < 5 * 256 * 64) {
        int p = idx / 16384, r = idx % 16384;
        int n = r / 64, kl = r % 64;
        float v = W1[(size_t)(p * 64 + kl) * D_HID + n];
        __nv_bfloat16 h = __float2bfloat16_rn(v);
        float lo = v - __bfloat162float(h);
        uint32_t off = (uint32_t)p * 32768u + pswz(n, 2 * kl);
        *(__nv_bfloat16*)((char*)gW1T_h + off) = h;
        *(__nv_bfloat16*)((char*)gW1T_l + off) = __float2bfloat16_rn(lo);
    } else if (idx < 5 * 256 * 64 + 4 * 64 * 64) {
        int j = idx - 5 * 256 * 64;
        int p = j / 4096, r = j % 4096;
        int n = r / 64, kl = r % 64;
        float v = W2[(size_t)(p * 64 + kl) * D_OUT + n];
        __nv_bfloat16 h = __float2bfloat16_rn(v);
        float lo = v - __bfloat162float(h);
        uint32_t off = (uint32_t)p * 8192u + pswz(n, 2 * kl);
        *(__nv_bfloat16*)((char*)gW2T_h + off) = h;
        *(__nv_bfloat16*)((char*)gW2T_l + off) = __float2bfloat16_rn(lo);
    }
}

// ---------------- kernel 1: P table via bf16-split MMA ----------------
// CTA: 128 nodes x 512 cols (4 chunks of 128). smem 128KB.
__global__ __launch_bounds__(256) void k_pre(
    const float* __restrict__ NF, const float* __restrict__ b1)
{
    extern __shared__ char sm[];
    // [0,32K) sAh (2 panels), [32K,64K) sAl, [64K,96K) sBh (2 panels), [96K,128K) sBl
    const uint32_t uA_h = s2u(sm), uA_l = uA_h + 32768;
    const uint32_t uB_h = uA_h + 65536, uB_l = uA_h + 98304;

    const int tid = threadIdx.x, lane = tid & 31, wid = tid >> 5;
    const int wm = wid & 3, wn = wid >> 2;
    const int m0 = blockIdx.x * 128;

    // lane components for ldmatrix address patterns
    const uint32_t a_row = (lane & 7) + ((lane >> 3) & 1) * 8;
    const uint32_t a_kb  = (lane >> 4) * 16;
    const uint32_t b_row = (lane & 7) + (lane >> 4) * 8;
    const uint32_t b_kb  = ((lane >> 3) & 1) * 16;

    // load A (NF tile), split to hi/lo panels
    #pragma unroll
    for (int t = 0; t < 32; t++) {
        int idx = tid + t * 256;           // 128 rows x 64 k-pairs
        int e = idx >> 6, kp = idx & 63;
        int gm = m0 + e;
        float2 v = make_float2(0.f, 0.f);
        if (gm < N_NODES) v = *(const float2*)(NF + (size_t)gm * D_NODE + 2 * kp);
        uint32_t hi, lo; split2(v.x, v.y, hi, lo);
        uint32_t off = (uint32_t)(kp >> 5) * 16384u + pswz(e, (kp & 31) * 4);
        *(uint32_t*)(sm + off) = hi;
        *(uint32_t*)(sm + 32768 + off) = lo;
    }
    __syncthreads();

    for (int c = 0; c < 4; c++) {
        // copy B panels from pre-swizzled image
        const int p0 = (c < 2) ? 0 : 2;
        const int wc0 = (c & 1) * 128;
        const uint32_t* srcH = (const uint32_t*)(gW1T_h) ;
        const uint32_t* srcL = (const uint32_t*)(gW1T_l) ;
        #pragma unroll
        for (int d = 0; d < 2; d++) {
            size_t so = ((size_t)(p0 + d) * 16384 + (size_t)wc0 * 64) / 2; // words
            #pragma unroll
            for (int t = 0; t < 16; t++) {
                int w = tid + t * 256;   // 4096 words per panel
                ((uint32_t*)(sm + 65536 + d * 16384))[w] = srcH[so + w];
                ((uint32_t*)(sm + 98304 + d * 16384))[w] = srcL[so + w];
            }
        }
        __syncthreads();

        float acc[2][8][4];
        #pragma unroll
        for (int i = 0; i < 2; i++)
            #pragma unroll
            for (int j = 0; j < 8; j++)
                #pragma unroll
                for (int r = 0; r < 4; r++) acc[i][j][r] = 0.f;

        #pragma unroll
        for (int ks = 0; ks < 8; ks++) {
            const uint32_t pan = (uint32_t)(ks >> 2) * 16384u;
            const uint32_t kb = (ks & 3) * 32;
            uint32_t Ah[2][4], Al[2][4], Bh[4][4], Bl[4][4];
            #pragma unroll
            for (int mt = 0; mt < 2; mt++) {
                uint32_t row = wm * 32 + mt * 16 + a_row;
                uint32_t off = pan + pswz(row, kb + a_kb);
                ldm_x4(Ah[mt], uA_h + off);
                ldm_x4(Al[mt], uA_l + off);
            }
            #pragma unroll
            for (int np = 0; np < 4; np++) {
                uint32_t row = wn * 64 + np * 16 + b_row;
                uint32_t off = pan + pswz(row, kb + b_kb);
                ldm_x4(Bh[np], uB_h + off);
                ldm_x4(Bl[np], uB_l + off);
            }
            #pragma unroll
            for (int mt = 0; mt < 2; mt++)
                #pragma unroll
                for (int nt = 0; nt < 8; nt++) {
                    const uint32_t* bh = &Bh[nt >> 1][(nt & 1) * 2];
                    const uint32_t* bl = &Bl[nt >> 1][(nt & 1) * 2];
                    mma16816(acc[mt][nt], Ah[mt], bh);
                    mma16816(acc[mt][nt], Ah[mt], bl);
                    mma16816(acc[mt][nt], Al[mt], bh);
                }
        }

        // write P chunk (+b1 on the Pa half)
        const int g = lane >> 2, tg2 = (lane & 3) * 2;
        #pragma unroll
        for (int mt = 0; mt < 2; mt++) {
            #pragma unroll
            for (int rr = 0; rr < 2; rr++) {
                int gm = m0 + wm * 32 + mt * 16 + g + rr * 8;
                if (gm < N_NODES) {
                    #pragma unroll
                    for (int nt = 0; nt < 8; nt++) {
                        int col = c * 128 + wn * 64 + nt * 8 + tg2;
                        float2 o;
                        o.x = acc[mt][nt][rr * 2 + 0];
                        o.y = acc[mt][nt][rr * 2 + 1];
                        if (c < 2) { o.x += b1[col]; o.y += b1[col + 1]; }
                        *(float2*)(g_P + (size_t)gm * 512 + col) = o;
                    }
                }
            }
        }
        __syncthreads();
    }
}

// ---------------- kernel 2: fused edge MLP via bf16-split MMA ----------------
// smem 192KB: [0,64K) region X, [64K,128K) sHh (4 panels), [128K,192K) sHl
__global__ __launch_bounds__(256) void k_edge(
    const int* __restrict__ EIw, const float* __restrict__ EA,
    const float* __restrict__ b2, float* __restrict__ out)
{
    extern __shared__ char sm[];
    const uint32_t uX = s2u(sm);
    const uint32_t uAh = uX, uAl = uX + 16384;        // GEMM1 A (EA)
    const uint32_t uBh = uX + 32768, uBl = uX + 49152; // GEMM1 B (W1c half)
    const uint32_t uW2h = uX, uW2l = uX + 32768;       // GEMM2 B (reuses X)
    const uint32_t uHh = uX + 65536, uHl = uX + 131072;

    __shared__ int sRow[128], sCol[128];

    const int tid = threadIdx.x, lane = tid & 31, wid = tid >> 5;
    const int wm = wid & 3, wn = wid >> 2;
    const int e0 = blockIdx.x * 128;
    const int g = lane >> 2, tg2 = (lane & 3) * 2;

    const uint32_t a_row = (lane & 7) + ((lane >> 3) & 1) * 8;
    const uint32_t a_kb  = (lane >> 4) * 16;
    const uint32_t b_row = (lane & 7) + (lane >> 4) * 8;
    const uint32_t b_kb  = ((lane >> 3) & 1) * 16;

    if (tid < 128) {
        int e = e0 + tid;
        int r = 0, c = 0;
        if (e < N_EDGES) {
            if (g_idx64) { r = EIw[(size_t)2 * e]; c = EIw[(size_t)2 * (N_EDGES + e)]; }
            else         { r = EIw[e];             c = EIw[(size_t)N_EDGES + e]; }
        }
        sRow[tid] = min(max(r, 0), N_NODES - 1);
        sCol[tid] = min(max(c, 0), N_NODES - 1);
    }
    // EA tile -> bf16 split panel [128e][64k]
    #pragma unroll
    for (int t = 0; t < 16; t++) {
        int idx = tid + t * 256;           // 128 e x 32 k-pairs
        int e = idx >> 5, kp = idx & 31;
        int ge = e0 + e;
        float2 v = make_float2(0.f, 0.f);
        if (ge < N_EDGES) v = *(const float2*)(EA + (size_t)ge * D_EDGE + 2 * kp);
        uint32_t hi, lo; split2(v.x, v.y, hi, lo);
        uint32_t off = pswz(e, kp * 4);
        *(uint32_t*)(sm + off) = hi;
        *(uint32_t*)(sm + 16384 + off) = lo;
    }
    __syncthreads();

    // ---- GEMM1: two 128-wide hidden halves ----
    for (int half = 0; half < 2; half++) {
        // copy W1c half panel [128n][64k] from pre-swizzled image (panel 4)
        {
            size_t so = ((size_t)4 * 16384 + (size_t)half * 128 * 64) / 2; // words
            const uint32_t* srcH = (const uint32_t*)gW1T_h;
            const uint32_t* srcL = (const uint32_t*)gW1T_l;
            #pragma unroll
            for (int t = 0; t < 16; t++) {
                int w = tid + t * 256;     // 4096 words
                ((uint32_t*)(sm + 32768))[w] = srcH[so + w];
                ((uint32_t*)(sm + 49152))[w] = srcL[so + w];
            }
        }
        __syncthreads();

        float acc[2][8][4];
        #pragma unroll
        for (int i = 0; i < 2; i++)
            #pragma unroll
            for (int j = 0; j < 8; j++)
                #pragma unroll
                for (int r = 0; r < 4; r++) acc[i][j][r] = 0.f;

        #pragma unroll
        for (int ks = 0; ks < 4; ks++) {
            const uint32_t kb = ks * 32;
            uint32_t Ah[2][4], Al[2][4], Bh[4][4], Bl[4][4];
            #pragma unroll
            for (int mt = 0; mt < 2; mt++) {
                uint32_t off = pswz(wm * 32 + mt * 16 + a_row, kb + a_kb);
                ldm_x4(Ah[mt], uAh + off);
                ldm_x4(Al[mt], uAl + off);
            }
            #pragma unroll
            for (int np = 0; np < 4; np++) {
                uint32_t off = pswz(wn * 64 + np * 16 + b_row, kb + b_kb);
                ldm_x4(Bh[np], uBh + off);
                ldm_x4(Bl[np], uBl + off);
            }
            #pragma unroll
            for (int mt = 0; mt < 2; mt++)
                #pragma unroll
                for (int nt = 0; nt < 8; nt++) {
                    const uint32_t* bh = &Bh[nt >> 1][(nt & 1) * 2];
                    const uint32_t* bl = &Bl[nt >> 1][(nt & 1) * 2];
                    mma16816(acc[mt][nt], Ah[mt], bh);
                    mma16816(acc[mt][nt], Ah[mt], bl);
                    mma16816(acc[mt][nt], Al[mt], bh);
                }
        }

        // epilogue: gather P (pa has b1 folded), relu, split-store h panels
        #pragma unroll
        for (int mt = 0; mt < 2; mt++) {
            #pragma unroll
            for (int rr = 0; rr < 2; rr++) {
                int e = wm * 32 + mt * 16 + g + rr * 8;
                const float* pa = g_P + (size_t)sRow[e] * 512;
                const float* pb = g_P + (size_t)sCol[e] * 512 + 256;
                #pragma unroll
                for (int nt = 0; nt < 8; nt++) {
                    int col = half * 128 + wn * 64 + nt * 8 + tg2;   // 0..255
                    float2 va = *(const float2*)(pa + col);
                    float2 vb = *(const float2*)(pb + col);
                    float h0 = fmaxf(acc[mt][nt][rr * 2 + 0] + va.x + vb.x, 0.f);
                    float h1 = fmaxf(acc[mt][nt][rr * 2 + 1] + va.y + vb.y, 0.f);
                    uint32_t hi, lo; split2(h0, h1, hi, lo);
                    uint32_t off = (uint32_t)(col >> 6) * 16384u + pswz(e, (col & 63) * 2);
                    *(uint32_t*)(sm + 65536 + off) = hi;
                    *(uint32_t*)(sm + 131072 + off) = lo;
                }
            }
        }
        __syncthreads();
    }

    // ---- GEMM2: out = h @ W2 ----
    {   // copy W2 panel images into region X
        const uint32_t* srcH = (const uint32_t*)gW2T_h;
        const uint32_t* srcL = (const uint32_t*)gW2T_l;
        #pragma unroll
        for (int t = 0; t < 32; t++) {
            int w = tid + t * 256;         // 8192 words each
            ((uint32_t*)(sm))[w] = srcH[w];
            ((uint32_t*)(sm + 32768))[w] = srcL[w];
        }
    }
    __syncthreads();

    float d[8][4];
    #pragma unroll
    for (int j = 0; j < 8; j++)
        #pragma unroll
        for (int r = 0; r < 4; r++) d[j][r] = 0.f;

    #pragma unroll 4
    for (int ks = 0; ks < 16; ks++) {
        const uint32_t hp = (uint32_t)(ks >> 2) * 16384u;  // h panel
        const uint32_t wp = (uint32_t)(ks >> 2) * 8192u;   // W2 panel
        const uint32_t kb = (ks & 3) * 32;
        uint32_t Ah[4], Al[4], Bh[4][4], Bl[4][4];
        {
            uint32_t off = hp + pswz(wid * 16 + a_row, kb + a_kb);
            ldm_x4(Ah, uHh + off);
            ldm_x4(Al, uHl + off);
        }
        #pragma unroll
        for (int np = 0; np < 4; np++) {
            uint32_t off = wp + pswz(np * 16 + b_row, kb + b_kb);
            ldm_x4(Bh[np], uW2h + off);
            ldm_x4(Bl[np], uW2l + off);
        }
        #pragma unroll
        for (int nt = 0; nt < 8; nt++) {
            const uint32_t* bh = &Bh[nt >> 1][(nt & 1) * 2];
            const uint32_t* bl = &Bl[nt >> 1][(nt & 1) * 2];
            mma16816(d[nt], Ah, bh);
            mma16816(d[nt], Ah, bl);
            mma16816(d[nt], Al, bh);
        }
    }

    #pragma unroll
    for (int rr = 0; rr < 2; rr++) {
        int ge = e0 + wid * 16 + g + rr * 8;
        if (ge < N_EDGES) {
            #pragma unroll
            for (int nt = 0; nt < 8; nt++) {
                int n = nt * 8 + tg2;
                float2 bb = *(const float2*)(b2 + n);
                float2 o;
                o.x = d[nt][rr * 2 + 0] + bb.x;
                o.y = d[nt][rr * 2 + 1] + bb.y;
                *(float2*)(out + (size_t)ge * D_OUT + n) = o;
            }
        }
    }
}

// ---------------------------------------------------------------------------
extern "C" void kernel_launch(void* const* d_in, const int* in_sizes, int n_in,
                              void* d_out, int out_size) {
    const float* NF  = (const float*)d_in[0];
    const int*   EIw = (const int*)d_in[1];
    const float* EA  = (const float*)d_in[2];
    const float* W1  = (const float*)d_in[3];
    const float* b1  = (const float*)d_in[4];
    const float* W2  = (const float*)d_in[5];
    const float* b2  = (const float*)d_in[6];
    float* out = (float*)d_out;

    static int attr_set = 0;
    if (!attr_set) {
        cudaFuncSetAttribute(k_pre, cudaFuncAttributeMaxDynamicSharedMemorySize, 131072);
        cudaFuncSetAttribute(k_edge, cudaFuncAttributeMaxDynamicSharedMemorySize, 196608);
        attr_set = 1;
    }

    k_detect<<<1, 32>>>(EIw);
    k_convw<<<(5 * 256 * 64 + 4 * 64 * 64 + 255) / 256, 256>>>(W1, W2);
    k_pre<<<(N_NODES + 127) / 128, 256, 131072>>>(NF, b1);
    k_edge<<<(N_EDGES + 127) / 128, 256, 196608>>>(EIw, EA, b2, out);
}

// round 7
// speedup vs baseline: 2.4869x; 1.2940x over previous
#include <cuda_runtime.h>
#include <cuda_bf16.h>
#include <cstdint>

#define N_NODES 50000
#define N_EDGES 500000
#define D_NODE  128
#define D_EDGE  64
#define D_HID   256
#define D_OUT   64

// P[node][0:256] = nf@W1a + b1 ; P[node][256:512] = nf@W1b
__device__ float g_P[(size_t)N_NODES * 512];
// W1^T bf16 split, 5 k-panels of [256 n][64 k], swizzled 128B rows
__device__ __nv_bfloat16 gW1T_h[5 * 256 * 64];
__device__ __nv_bfloat16 gW1T_l[5 * 256 * 64];
// W2^T bf16 split, 4 k-panels of [64 n][64 k]
__device__ __nv_bfloat16 gW2T_h[4 * 64 * 64];
__device__ __nv_bfloat16 gW2T_l[4 * 64 * 64];
__device__ int g_idx64;

// ---------------- helpers ----------------
__device__ __forceinline__ uint32_t s2u(const void* p) {
    return (uint32_t)__cvta_generic_to_shared(p);
}
__device__ __forceinline__ uint32_t pswz(uint32_t row, uint32_t kbyte) {
    return row * 128u + (kbyte ^ ((row & 7u) << 4));
}
__device__ __forceinline__ void ldm_x4(uint32_t* r, uint32_t addr) {
    asm volatile("ldmatrix.sync.aligned.m8n8.x4.shared.b16 {%0,%1,%2,%3}, [%4];"
        : "=r"(r[0]), "=r"(r[1]), "=r"(r[2]), "=r"(r[3]) : "r"(addr));
}
__device__ __forceinline__ void mma16816(float* c, const uint32_t* a, const uint32_t* b) {
    asm volatile("mma.sync.aligned.m16n8k16.row.col.f32.bf16.bf16.f32 "
        "{%0,%1,%2,%3}, {%4,%5,%6,%7}, {%8,%9}, {%0,%1,%2,%3};"
        : "+f"(c[0]), "+f"(c[1]), "+f"(c[2]), "+f"(c[3])
        : "r"(a[0]), "r"(a[1]), "r"(a[2]), "r"(a[3]), "r"(b[0]), "r"(b[1]));
}
__device__ __forceinline__ uint32_t packbf(float a, float b) {
    __nv_bfloat162 t;
    t.x = __float2bfloat16_rn(a); t.y = __float2bfloat16_rn(b);
    return *reinterpret_cast<uint32_t*>(&t);
}
__device__ __forceinline__ void split2(float a, float b, uint32_t& hi, uint32_t& lo) {
    __nv_bfloat16 ha = __float2bfloat16_rn(a), hb = __float2bfloat16_rn(b);
    float la = a - __bfloat162float(ha), lb = b - __bfloat162float(hb);
    __nv_bfloat162 th; th.x = ha; th.y = hb;
    hi = *reinterpret_cast<uint32_t*>(&th);
    lo = packbf(la, lb);
}

// ---------------- dtype detect ----------------
__global__ void k_detect(const int* __restrict__ EIw) {
    if (threadIdx.x == 0 && blockIdx.x == 0) {
        int allzero = 1;
        #pragma unroll 1
        for (int i = 0; i < 64; i++)
            if (EIw[2 * i + 1] != 0) { allzero = 0; break; }
        g_idx64 = allzero;
    }
}

// ---------------- weight conversion ----------------
__global__ __launch_bounds__(256) void k_convw(
    const float* __restrict__ W1, const float* __restrict__ W2)
{
    int idx = blockIdx.x * 256 + threadIdx.x;
    if (idx < 5 * 256 * 64) {
        int p = idx / 16384, r = idx % 16384;
        int n = r / 64, kl = r % 64;
        float v = W1[(size_t)(p * 64 + kl) * D_HID + n];
        __nv_bfloat16 h = __float2bfloat16_rn(v);
        float lo = v - __bfloat162float(h);
        uint32_t off = (uint32_t)p * 32768u + pswz(n, 2 * kl);
        *(__nv_bfloat16*)((char*)gW1T_h + off) = h;
        *(__nv_bfloat16*)((char*)gW1T_l + off) = __float2bfloat16_rn(lo);
    } else if (idx < 5 * 256 * 64 + 4 * 64 * 64) {
        int j = idx - 5 * 256 * 64;
        int p = j / 4096, r = j % 4096;
        int n = r / 64, kl = r % 64;
        float v = W2[(size_t)(p * 64 + kl) * D_OUT + n];
        __nv_bfloat16 h = __float2bfloat16_rn(v);
        float lo = v - __bfloat162float(h);
        uint32_t off = (uint32_t)p * 8192u + pswz(n, 2 * kl);
        *(__nv_bfloat16*)((char*)gW2T_h + off) = h;
        *(__nv_bfloat16*)((char*)gW2T_l + off) = __float2bfloat16_rn(lo);
    }
}

// ---------------- kernel 1: P table via bf16-split MMA ----------------
__global__ __launch_bounds__(256) void k_pre(
    const float* __restrict__ NF, const float* __restrict__ b1)
{
    extern __shared__ char sm[];
    const uint32_t uA_h = s2u(sm), uA_l = uA_h + 32768;
    const uint32_t uB_h = uA_h + 65536, uB_l = uA_h + 98304;

    const int tid = threadIdx.x, lane = tid & 31, wid = tid >> 5;
    const int wm = wid & 3, wn = wid >> 2;
    const int m0 = blockIdx.x * 128;

    const uint32_t a_row = (lane & 7) + ((lane >> 3) & 1) * 8;
    const uint32_t a_kb  = (lane >> 4) * 16;
    const uint32_t b_row = (lane & 7) + (lane >> 4) * 8;
    const uint32_t b_kb  = ((lane >> 3) & 1) * 16;

    #pragma unroll
    for (int t = 0; t < 32; t++) {
        int idx = tid + t * 256;
        int e = idx >> 6, kp = idx & 63;
        int gm = m0 + e;
        float2 v = make_float2(0.f, 0.f);
        if (gm < N_NODES) v = *(const float2*)(NF + (size_t)gm * D_NODE + 2 * kp);
        uint32_t hi, lo; split2(v.x, v.y, hi, lo);
        uint32_t off = (uint32_t)(kp >> 5) * 16384u + pswz(e, (kp & 31) * 4);
        *(uint32_t*)(sm + off) = hi;
        *(uint32_t*)(sm + 32768 + off) = lo;
    }
    __syncthreads();

    for (int c = 0; c < 4; c++) {
        const int p0 = (c < 2) ? 0 : 2;
        const int wc0 = (c & 1) * 128;
        const uint32_t* srcH = (const uint32_t*)(gW1T_h);
        const uint32_t* srcL = (const uint32_t*)(gW1T_l);
        #pragma unroll
        for (int d = 0; d < 2; d++) {
            size_t so = ((size_t)(p0 + d) * 16384 + (size_t)wc0 * 64) / 2;
            #pragma unroll
            for (int t = 0; t < 16; t++) {
                int w = tid + t * 256;
                ((uint32_t*)(sm + 65536 + d * 16384))[w] = srcH[so + w];
                ((uint32_t*)(sm + 98304 + d * 16384))[w] = srcL[so + w];
            }
        }
        __syncthreads();

        float acc[2][8][4];
        #pragma unroll
        for (int i = 0; i < 2; i++)
            #pragma unroll
            for (int j = 0; j < 8; j++)
                #pragma unroll
                for (int r = 0; r < 4; r++) acc[i][j][r] = 0.f;

        #pragma unroll
        for (int ks = 0; ks < 8; ks++) {
            const uint32_t pan = (uint32_t)(ks >> 2) * 16384u;
            const uint32_t kb = (ks & 3) * 32;
            uint32_t Ah[2][4], Al[2][4], Bh[4][4], Bl[4][4];
            #pragma unroll
            for (int mt = 0; mt < 2; mt++) {
                uint32_t row = wm * 32 + mt * 16 + a_row;
                uint32_t off = pan + pswz(row, kb + a_kb);
                ldm_x4(Ah[mt], uA_h + off);
                ldm_x4(Al[mt], uA_l + off);
            }
            #pragma unroll
            for (int np = 0; np < 4; np++) {
                uint32_t row = wn * 64 + np * 16 + b_row;
                uint32_t off = pan + pswz(row, kb + b_kb);
                ldm_x4(Bh[np], uB_h + off);
                ldm_x4(Bl[np], uB_l + off);
            }
            #pragma unroll
            for (int mt = 0; mt < 2; mt++)
                #pragma unroll
                for (int nt = 0; nt < 8; nt++) {
                    const uint32_t* bh = &Bh[nt >> 1][(nt & 1) * 2];
                    const uint32_t* bl = &Bl[nt >> 1][(nt & 1) * 2];
                    mma16816(acc[mt][nt], Ah[mt], bh);
                    mma16816(acc[mt][nt], Ah[mt], bl);
                    mma16816(acc[mt][nt], Al[mt], bh);
                }
        }

        const int g = lane >> 2, tg2 = (lane & 3) * 2;
        #pragma unroll
        for (int mt = 0; mt < 2; mt++) {
            #pragma unroll
            for (int rr = 0; rr < 2; rr++) {
                int gm = m0 + wm * 32 + mt * 16 + g + rr * 8;
                if (gm < N_NODES) {
                    #pragma unroll
                    for (int nt = 0; nt < 8; nt++) {
                        int col = c * 128 + wn * 64 + nt * 8 + tg2;
                        float2 o;
                        o.x = acc[mt][nt][rr * 2 + 0];
                        o.y = acc[mt][nt][rr * 2 + 1];
                        if (c < 2) { o.x += b1[col]; o.y += b1[col + 1]; }
                        *(float2*)(g_P + (size_t)gm * 512 + col) = o;
                    }
                }
            }
        }
        __syncthreads();
    }
}

// ---------------- kernel 2: register-chained edge MLP ----------------
// 64 edges/CTA, 48KB smem, 2 CTAs/SM. h never hits smem: GEMM1 accumulators
// are gathered/relu'd/split in regs and fed directly as GEMM2 A-fragments.
__global__ __launch_bounds__(256, 2) void k_edge(
    const int* __restrict__ EIw, const float* __restrict__ EA,
    const float* __restrict__ b2, float* __restrict__ out)
{
    extern __shared__ char sm[];
    const uint32_t uBase = s2u(sm);
    const uint32_t uEAh = uBase, uEAl = uBase + 8192;
    const uint32_t uWBh = uBase + 16384, uWBl = uBase + 32768;
    float* red = (float*)(sm + 16384);   // reuses WB region after GEMM2

    __shared__ int sRow[64], sCol[64];

    const int tid = threadIdx.x, lane = tid & 31, wid = tid >> 5;
    const int wm = wid & 3, wn = wid >> 2;   // 4 x 2 warp grid
    const int e0 = blockIdx.x * 64;
    const int g = lane >> 2, tg2 = (lane & 3) * 2;

    const uint32_t a_row = (lane & 7) + ((lane >> 3) & 1) * 8;
    const uint32_t a_kb  = (lane >> 4) * 16;
    const uint32_t b_row = (lane & 7) + (lane >> 4) * 8;
    const uint32_t b_kb  = ((lane >> 3) & 1) * 16;

    if (tid < 64) {
        int e = e0 + tid;
        int r = 0, c = 0;
        if (e < N_EDGES) {
            if (g_idx64) { r = EIw[(size_t)2 * e]; c = EIw[(size_t)2 * (N_EDGES + e)]; }
            else         { r = EIw[e];             c = EIw[(size_t)N_EDGES + e]; }
        }
        sRow[tid] = min(max(r, 0), N_NODES - 1);
        sCol[tid] = min(max(c, 0), N_NODES - 1);
    }
    // EA tile [64e][64k] -> bf16 split panels
    #pragma unroll
    for (int t = 0; t < 8; t++) {
        int idx = tid + t * 256;
        int e = idx >> 5, kp = idx & 31;
        int ge = e0 + e;
        float2 v = make_float2(0.f, 0.f);
        if (ge < N_EDGES) v = *(const float2*)(EA + (size_t)ge * D_EDGE + 2 * kp);
        uint32_t hi, lo; split2(v.x, v.y, hi, lo);
        uint32_t off = pswz(e, kp * 4);
        *(uint32_t*)(sm + off) = hi;
        *(uint32_t*)(sm + 8192 + off) = lo;
    }
    __syncthreads();

    float d[8][4];
    #pragma unroll
    for (int j = 0; j < 8; j++)
        #pragma unroll
        for (int r = 0; r < 4; r++) d[j][r] = 0.f;

    const int eg = wm * 16 + g;

    #pragma unroll 1
    for (int h = 0; h < 2; h++) {
        // ---- load W1c half panel [128n][64k] into WB (4096 words each) ----
        {
            size_t so = 32768 + (size_t)h * 4096;   // words: panel 4, half h
            #pragma unroll
            for (int t = 0; t < 16; t++) {
                int w = tid + t * 256;
                ((uint32_t*)(sm + 16384))[w] = ((const uint32_t*)gW1T_h)[so + w];
                ((uint32_t*)(sm + 32768))[w] = ((const uint32_t*)gW1T_l)[so + w];
            }
        }
        __syncthreads();

        // ---- GEMM1: acc[16e x 64hid] ----
        float acc[8][4];
        #pragma unroll
        for (int j = 0; j < 8; j++)
            #pragma unroll
            for (int r = 0; r < 4; r++) acc[j][r] = 0.f;

        #pragma unroll
        for (int ks = 0; ks < 4; ks++) {
            const uint32_t kb = ks * 32;
            uint32_t Ah[4], Al[4], Bh[4][4], Bl[4][4];
            {
                uint32_t off = pswz(wm * 16 + a_row, kb + a_kb);
                ldm_x4(Ah, uEAh + off);
                ldm_x4(Al, uEAl + off);
            }
            #pragma unroll
            for (int np = 0; np < 4; np++) {
                uint32_t off = pswz(wn * 64 + np * 16 + b_row, kb + b_kb);
                ldm_x4(Bh[np], uWBh + off);
                ldm_x4(Bl[np], uWBl + off);
            }
            #pragma unroll
            for (int nt = 0; nt < 8; nt++) {
                const uint32_t* bh = &Bh[nt >> 1][(nt & 1) * 2];
                const uint32_t* bl = &Bl[nt >> 1][(nt & 1) * 2];
                mma16816(acc[nt], Ah, bh);
                mma16816(acc[nt], Ah, bl);
                mma16816(acc[nt], Al, bh);
            }
        }
        __syncthreads();

        // ---- swap WB -> W2 k-panels 2h,2h+1 (4096 words total each of h/l) ----
        {
            size_t so = (size_t)h * 4096;   // words: two 2048-word panels
            #pragma unroll
            for (int t = 0; t < 16; t++) {
                int w = tid + t * 256;
                ((uint32_t*)(sm + 16384))[w] = ((const uint32_t*)gW2T_h)[so + w];
                ((uint32_t*)(sm + 32768))[w] = ((const uint32_t*)gW2T_l)[so + w];
            }
        }
        __syncthreads();

        // ---- epilogue (gather P, relu, split) + GEMM2 partial, in regs ----
        const int pc = h * 128 + wn * 64;
        const float* paG  = g_P + (size_t)sRow[eg]     * 512 + pc;
        const float* paG8 = g_P + (size_t)sRow[eg + 8] * 512 + pc;
        const float* pbG  = g_P + (size_t)sCol[eg]     * 512 + 256 + pc;
        const float* pbG8 = g_P + (size_t)sCol[eg + 8] * 512 + 256 + pc;
        const uint32_t w2h = uWBh + wn * 8192, w2l = uWBl + wn * 8192;

        #pragma unroll
        for (int j = 0; j < 4; j++) {
            const int c0 = j * 16 + tg2, c1 = c0 + 8;
            float2 va0 = __ldg((const float2*)(paG  + c0));
            float2 vb0 = __ldg((const float2*)(pbG  + c0));
            float2 wa0 = __ldg((const float2*)(paG8 + c0));
            float2 wb0 = __ldg((const float2*)(pbG8 + c0));
            float2 va1 = __ldg((const float2*)(paG  + c1));
            float2 vb1 = __ldg((const float2*)(pbG  + c1));
            float2 wa1 = __ldg((const float2*)(paG8 + c1));
            float2 wb1 = __ldg((const float2*)(pbG8 + c1));

            float x00 = fmaxf(acc[2*j][0]   + va0.x + vb0.x, 0.f);
            float x01 = fmaxf(acc[2*j][1]   + va0.y + vb0.y, 0.f);
            float x10 = fmaxf(acc[2*j][2]   + wa0.x + wb0.x, 0.f);
            float x11 = fmaxf(acc[2*j][3]   + wa0.y + wb0.y, 0.f);
            float y00 = fmaxf(acc[2*j+1][0] + va1.x + vb1.x, 0.f);
            float y01 = fmaxf(acc[2*j+1][1] + va1.y + vb1.y, 0.f);
            float y10 = fmaxf(acc[2*j+1][2] + wa1.x + wb1.x, 0.f);
            float y11 = fmaxf(acc[2*j+1][3] + wa1.y + wb1.y, 0.f);

            // C-tile pair -> A-fragment (m16k16), hi/lo split
            uint32_t a_hi[4], a_lo[4];
            split2(x00, x01, a_hi[0], a_lo[0]);   // row g,   k tg2..+1
            split2(x10, x11, a_hi[1], a_lo[1]);   // row g+8, k tg2..+1
            split2(y00, y01, a_hi[2], a_lo[2]);   // row g,   k tg2+8..+9
            split2(y10, y11, a_hi[3], a_lo[3]);   // row g+8, k tg2+8..+9

            #pragma unroll
            for (int np = 0; np < 4; np++) {
                uint32_t Bh4[4], Bl4[4];
                uint32_t off = pswz(np * 16 + b_row, j * 32 + b_kb);
                ldm_x4(Bh4, w2h + off);
                ldm_x4(Bl4, w2l + off);
                #pragma unroll
                for (int pr = 0; pr < 2; pr++) {
                    int nt = np * 2 + pr;
                    mma16816(d[nt], a_hi, &Bh4[pr * 2]);
                    mma16816(d[nt], a_hi, &Bl4[pr * 2]);
                    mma16816(d[nt], a_lo, &Bh4[pr * 2]);
                }
            }
        }
        __syncthreads();   // WB free before next half / reduction
    }

    // ---- cross-wn reduction (stride-72 buffer in WB region) ----
    if (wn == 1) {
        #pragma unroll
        for (int nt = 0; nt < 8; nt++) {
            int n = nt * 8 + tg2;
            *(float2*)(red + (size_t)(wm * 16 + g) * 72 + n) =
                make_float2(d[nt][0], d[nt][1]);
            *(float2*)(red + (size_t)(wm * 16 + g + 8) * 72 + n) =
                make_float2(d[nt][2], d[nt][3]);
        }
    }
    __syncthreads();
    if (wn == 0) {
        #pragma unroll
        for (int rr = 0; rr < 2; rr++) {
            int el = wm * 16 + g + rr * 8;
            int ge = e0 + el;
            if (ge < N_EDGES) {
                #pragma unroll
                for (int nt = 0; nt < 8; nt++) {
                    int n = nt * 8 + tg2;
                    float2 r2 = *(float2*)(red + (size_t)el * 72 + n);
                    float2 bb = *(const float2*)(b2 + n);
                    float2 o;
                    o.x = d[nt][rr * 2 + 0] + r2.x + bb.x;
                    o.y = d[nt][rr * 2 + 1] + r2.y + bb.y;
                    *(float2*)(out + (size_t)ge * D_OUT + n) = o;
                }
            }
        }
    }
}

// ---------------------------------------------------------------------------
extern "C" void kernel_launch(void* const* d_in, const int* in_sizes, int n_in,
                              void* d_out, int out_size) {
    const float* NF  = (const float*)d_in[0];
    const int*   EIw = (const int*)d_in[1];
    const float* EA  = (const float*)d_in[2];
    const float* W1  = (const float*)d_in[3];
    const float* b1  = (const float*)d_in[4];
    const float* W2  = (const float*)d_in[5];
    const float* b2  = (const float*)d_in[6];
    float* out = (float*)d_out;

    static int attr_set = 0;
    if (!attr_set) {
        cudaFuncSetAttribute(k_pre, cudaFuncAttributeMaxDynamicSharedMemorySize, 131072);
        cudaFuncSetAttribute(k_edge, cudaFuncAttributeMaxDynamicSharedMemorySize, 49152);
        attr_set = 1;
    }

    k_detect<<<1, 32>>>(EIw);
    k_convw<<<(5 * 256 * 64 + 4 * 64 * 64 + 255) / 256, 256>>>(W1, W2);
    k_pre<<<(N_NODES + 127) / 128, 256, 131072>>>(NF, b1);
    k_edge<<<(N_EDGES + 63) / 64, 256, 49152>>>(EIw, EA, b2, out);
}